// round 9
// baseline (speedup 1.0000x reference)
#include <cuda_runtime.h>
#include <cuda_bf16.h>
#include <math.h>
#include <stdint.h>

#define T_LEN   2048
#define HIDDEN  4096
#define NH      32
#define HD      128
#define QSIZE   (NH*HD)          // 4096
#define QKV_OUT 12288
#define EPS     1e-5f
#define ROPE_THETA 1000000.0f

// ---------------------------------------------------------------------------
// Scratch (static device globals: allocation-free per harness rules)
// ---------------------------------------------------------------------------
__device__ float g_qkv [(size_t)T_LEN * QKV_OUT];   // QKV output, fp32
__device__ float g_attn[(size_t)T_LEN * QSIZE];     // attn output, fp32

__device__ __nv_bfloat16 g_h_hi  [(size_t)T_LEN  * HIDDEN];
__device__ __nv_bfloat16 g_h_lo  [(size_t)T_LEN  * HIDDEN];
__device__ __nv_bfloat16 g_wq_hi [(size_t)QKV_OUT * HIDDEN];
__device__ __nv_bfloat16 g_wq_lo [(size_t)QKV_OUT * HIDDEN];
__device__ __nv_bfloat16 g_wo_hi [(size_t)HIDDEN * QSIZE];
__device__ __nv_bfloat16 g_wo_lo [(size_t)HIDDEN * QSIZE];
__device__ __nv_bfloat16 g_at_hi [(size_t)T_LEN  * QSIZE];
__device__ __nv_bfloat16 g_at_lo [(size_t)T_LEN  * QSIZE];

// ---------------------------------------------------------------------------
// PTX helpers — arch-neutral (sm_80-era) only: ldmatrix, mma.sync, cp.async.
// ---------------------------------------------------------------------------
__device__ __forceinline__ uint32_t smem_u32(const void* p) {
    uint32_t a;
    asm("{ .reg .u64 t; cvta.to.shared.u64 t, %1; cvt.u32.u64 %0, t; }"
        : "=r"(a) : "l"(p));
    return a;
}

#define CP_ASYNC16(dst, src) \
    asm volatile("cp.async.cg.shared.global [%0], [%1], 16;" \
                 :: "r"(dst), "l"(src) : "memory")
#define CP_COMMIT() asm volatile("cp.async.commit_group;" ::: "memory")
template<int N>
__device__ __forceinline__ void cp_wait() {
    asm volatile("cp.async.wait_group %0;" :: "n"(N) : "memory");
}

#define LDSM_X4(R, addr) \
    asm volatile("ldmatrix.sync.aligned.m8n8.x4.shared.b16 {%0,%1,%2,%3}, [%4];" \
                 : "=r"((R)[0]), "=r"((R)[1]), "=r"((R)[2]), "=r"((R)[3]) \
                 : "r"(addr))

__device__ __forceinline__ void mma16816(float* c, const uint32_t* a,
                                         uint32_t b0, uint32_t b1) {
    asm volatile(
        "mma.sync.aligned.m16n8k16.row.col.f32.bf16.bf16.f32 "
        "{%0,%1,%2,%3}, {%4,%5,%6,%7}, {%8,%9}, {%0,%1,%2,%3};"
        : "+f"(c[0]), "+f"(c[1]), "+f"(c[2]), "+f"(c[3])
        : "r"(a[0]), "r"(a[1]), "r"(a[2]), "r"(a[3]), "r"(b0), "r"(b1));
}

// ---------------------------------------------------------------------------
// fp32 -> bf16 hi/lo split (x = hi + lo, ~16 mantissa bits total)
// ---------------------------------------------------------------------------
__global__ void split_kernel(const float* __restrict__ x,
                             __nv_bfloat16* __restrict__ hi,
                             __nv_bfloat16* __restrict__ lo, int n4)
{
    int i = blockIdx.x * blockDim.x + threadIdx.x;
    if (i >= n4) return;
    float4 v = ((const float4*)x)[i];
    __nv_bfloat16 h0 = __float2bfloat16(v.x);
    __nv_bfloat16 h1 = __float2bfloat16(v.y);
    __nv_bfloat16 h2 = __float2bfloat16(v.z);
    __nv_bfloat16 h3 = __float2bfloat16(v.w);
    __nv_bfloat16 l0 = __float2bfloat16(v.x - __bfloat162float(h0));
    __nv_bfloat16 l1 = __float2bfloat16(v.y - __bfloat162float(h1));
    __nv_bfloat16 l2 = __float2bfloat16(v.z - __bfloat162float(h2));
    __nv_bfloat16 l3 = __float2bfloat16(v.w - __bfloat162float(h3));
    __nv_bfloat162* ph = (__nv_bfloat162*)&hi[(size_t)i * 4];
    __nv_bfloat162* pl = (__nv_bfloat162*)&lo[(size_t)i * 4];
    ph[0] = __nv_bfloat162(h0, h1); ph[1] = __nv_bfloat162(h2, h3);
    pl[0] = __nv_bfloat162(l0, l1); pl[1] = __nv_bfloat162(l2, l3);
}

// ---------------------------------------------------------------------------
// HMMA bf16x3 GEMM: C[m][n] = sum_k A[m][k]*B[n][k] (+bias[n]), K = 4096.
// CTA 128x256, 8 warps (2x4), warp tile 64x64 -> MMA:LDSM ratio 6 (was 4):
// smem-crossbar pressure per MMA cut 1.5x (the R5 binder).
// 3-stage cp.async pipeline, one __syncthreads per chunk.
// smem rows padded to 40 bf16 (80 B) -> ldmatrix conflict-free.
// ---------------------------------------------------------------------------
#define GK     4096
#define KC     32
#define NSTAGE 3
#define KSB    80                      // bytes per smem row (40 bf16)
#define OFF_AH 0
#define OFF_AL (128 * KSB)             // 10240
#define OFF_BH (2 * 128 * KSB)         // 20480
#define OFF_BL (OFF_BH + 256 * KSB)    // 41440? no: 20480+20480=40960
#define STG    (OFF_BH + 2 * 256 * KSB)  // 20480 + 40960 = 61440 B per stage
#define GEMM_SMEM (NSTAGE * STG)       // 184320 B

__global__ __launch_bounds__(256, 1)
void gemm_hmma(const __nv_bfloat16* __restrict__ Ah,
               const __nv_bfloat16* __restrict__ Al,
               const __nv_bfloat16* __restrict__ Bh,
               const __nv_bfloat16* __restrict__ Bl,
               const float* __restrict__ bias, float* __restrict__ C, int N)
{
    extern __shared__ char smem[];
    const uint32_t sb = smem_u32(smem);
    const int tid  = threadIdx.x;
    const int wid  = tid >> 5;
    const int lane = tid & 31;
    const int wm = (wid & 1) * 64;        // warp row offset (2 rows of warps)
    const int wn = (wid >> 1) * 64;       // warp col offset (4 cols of warps)
    const int bm = blockIdx.x * 128;
    const int bn = blockIdx.y * 256;

    float acc[4][8][4];
    #pragma unroll
    for (int mi = 0; mi < 4; mi++)
        #pragma unroll
        for (int ni = 0; ni < 8; ni++)
            #pragma unroll
            for (int j = 0; j < 4; j++) acc[mi][ni][j] = 0.f;

    // A loads: 2 threads/row, 32B contiguous each. B loads: 1 thread/row, 64B.
    const int ra  = tid >> 1;
    const int sa0 = (tid & 1) * 2;

    auto issue_load = [&](int c, int buf) {
        const uint32_t base = sb + (uint32_t)buf * STG;
        const int k0 = c * KC;
        #pragma unroll
        for (int s = 0; s < 2; s++) {
            uint32_t doff = (uint32_t)(ra * KSB + (sa0 + s) * 16);
            size_t ga = (size_t)(bm + ra) * GK + k0 + (sa0 + s) * 8;
            CP_ASYNC16(base + OFF_AH + doff, Ah + ga);
            CP_ASYNC16(base + OFF_AL + doff, Al + ga);
        }
        #pragma unroll
        for (int s = 0; s < 4; s++) {
            uint32_t doff = (uint32_t)(tid * KSB + s * 16);
            size_t gb = (size_t)(bn + tid) * GK + k0 + s * 8;
            CP_ASYNC16(base + OFF_BH + doff, Bh + gb);
            CP_ASYNC16(base + OFF_BL + doff, Bl + gb);
        }
    };

    const int NCHUNK = GK / KC;          // 128

    #pragma unroll
    for (int s = 0; s < NSTAGE - 1; s++) {
        issue_load(s, s);
        CP_COMMIT();
    }

    // ldmatrix lane addressing: row = lane&15, 16B col-group = lane>>4
    const uint32_t lrow = (uint32_t)(lane & 15) * KSB;
    const uint32_t lcol = (uint32_t)(lane >> 4) * 16;

    for (int c = 0; c < NCHUNK; c++) {
        cp_wait<NSTAGE - 2>();
        __syncthreads();   // readers of the slot being refilled are done

        if (c + NSTAGE - 1 < NCHUNK)
            issue_load(c + NSTAGE - 1, (c + NSTAGE - 1) % NSTAGE);
        CP_COMMIT();       // possibly-empty group keeps wait_group indexing

        const uint32_t base = sb + (uint32_t)(c % NSTAGE) * STG;
        const uint32_t aA = base + OFF_AH + (uint32_t)wm * KSB + lrow + lcol;
        const uint32_t aB = base + OFF_BH + (uint32_t)wn * KSB + lrow + lcol;

        #pragma unroll
        for (int ks = 0; ks < 2; ks++) {
            const uint32_t kof = ks * 32;
            uint32_t ah[4][4], al[4][4];
            #pragma unroll
            for (int mi = 0; mi < 4; mi++) {
                LDSM_X4(ah[mi], aA + mi * 16 * KSB + kof);
                LDSM_X4(al[mi], aA + (OFF_AL - OFF_AH) + mi * 16 * KSB + kof);
            }
            #pragma unroll
            for (int n16 = 0; n16 < 4; n16++) {
                uint32_t bh[4], bl[4];
                LDSM_X4(bh, aB + n16 * 16 * KSB + kof);
                LDSM_X4(bl, aB + (OFF_BL - OFF_BH) + n16 * 16 * KSB + kof);
                // term-major: hh (8 accs), then hl, then lh
                #pragma unroll
                for (int mi = 0; mi < 4; mi++)
                    #pragma unroll
                    for (int sub = 0; sub < 2; sub++)
                        mma16816(acc[mi][n16 * 2 + sub], ah[mi], bh[sub], bh[sub + 2]);
                #pragma unroll
                for (int mi = 0; mi < 4; mi++)
                    #pragma unroll
                    for (int sub = 0; sub < 2; sub++)
                        mma16816(acc[mi][n16 * 2 + sub], ah[mi], bl[sub], bl[sub + 2]);
                #pragma unroll
                for (int mi = 0; mi < 4; mi++)
                    #pragma unroll
                    for (int sub = 0; sub < 2; sub++)
                        mma16816(acc[mi][n16 * 2 + sub], al[mi], bh[sub], bh[sub + 2]);
            }
        }
    }

    // Epilogue: m16n8 acc layout: c0/c1 row=lane>>2 col=(lane&3)*2; c2/c3 row+8
    const int er = lane >> 2;
    const int ec = (lane & 3) * 2;
    #pragma unroll
    for (int mi = 0; mi < 4; mi++) {
        #pragma unroll
        for (int ni = 0; ni < 8; ni++) {
            int row = bm + wm + mi * 16 + er;
            int col = bn + wn + ni * 8 + ec;
            float b0 = bias ? bias[col] : 0.f;
            float b1 = bias ? bias[col + 1] : 0.f;
            float2 v0 = make_float2(acc[mi][ni][0] + b0, acc[mi][ni][1] + b1);
            float2 v1 = make_float2(acc[mi][ni][2] + b0, acc[mi][ni][3] + b1);
            *(float2*)&C[(size_t)row * N + col]       = v0;
            *(float2*)&C[(size_t)(row + 8) * N + col] = v1;
        }
    }
}

// ---------------------------------------------------------------------------
// Per-token RMSNorm (full 4096-dim q and k) + RoPE, in place on g_qkv.
// ---------------------------------------------------------------------------
__global__ void norm_rope_kernel(const int* __restrict__ positions,
                                 const float* __restrict__ qw,
                                 const float* __restrict__ kw)
{
    const int t   = blockIdx.x;
    const int tid = threadIdx.x;
    float* row = g_qkv + (size_t)t * QKV_OUT;

    __shared__ float red[256];
    __shared__ float s_scale_q, s_scale_k;

    float sq = 0.f, sk = 0.f;
    for (int i = tid; i < QSIZE; i += 256) {
        float x = row[i];         sq += x * x;
        float y = row[QSIZE + i]; sk += y * y;
    }

    red[tid] = sq; __syncthreads();
    for (int s = 128; s > 0; s >>= 1) {
        if (tid < s) red[tid] += red[tid + s];
        __syncthreads();
    }
    if (tid == 0) s_scale_q = rsqrtf(red[0] * (1.0f / QSIZE) + EPS);
    __syncthreads();

    red[tid] = sk; __syncthreads();
    for (int s = 128; s > 0; s >>= 1) {
        if (tid < s) red[tid] += red[tid + s];
        __syncthreads();
    }
    if (tid == 0) s_scale_k = rsqrtf(red[0] * (1.0f / QSIZE) + EPS);
    __syncthreads();

    const float scq = s_scale_q, sck = s_scale_k;
    const float pos = (float)positions[t];

    for (int idx = tid; idx < NH * 64; idx += 256) {
        int h = idx >> 6;
        int d = idx & 63;
        float inv_freq = powf(ROPE_THETA, -(float)d * (1.0f / 64.0f));
        float ang = pos * inv_freq;
        float sn, cs;
        sincosf(ang, &sn, &cs);

        int off = h * HD;
        {
            float x1 = row[off + d]      * scq * qw[off + d];
            float x2 = row[off + 64 + d] * scq * qw[off + 64 + d];
            row[off + d]      = x1 * cs - x2 * sn;
            row[off + 64 + d] = x2 * cs + x1 * sn;
        }
        {
            int offk = QSIZE + off;
            float x1 = row[offk + d]      * sck * kw[off + d];
            float x2 = row[offk + 64 + d] * sck * kw[off + 64 + d];
            row[offk + d]      = x1 * cs - x2 * sn;
            row[offk + 64 + d] = x2 * cs + x1 * sn;
        }
    }
}

// ---------------------------------------------------------------------------
// Flash-style causal attention, fp32 (known-good).
// ---------------------------------------------------------------------------
#define AT_BM 64
#define AT_BN 64
#define QK_STRIDE 132
#define SS_STRIDE 68

__global__ __launch_bounds__(256, 1)
void attn_kernel()
{
    extern __shared__ float asmem[];
    float* Qs = asmem;
    float* Ks = Qs + AT_BM * QK_STRIDE;
    float* Vs = Ks + AT_BN * QK_STRIDE;
    float* Ss = Vs + AT_BN * QK_STRIDE;

    const int qb  = blockIdx.x;
    const int h   = blockIdx.y;
    const int tid = threadIdx.x;
    const int r   = tid >> 2;
    const int c   = tid & 3;
    const float scale = 0.08838834764831845f;

    for (int f = tid; f < AT_BM * 32; f += 256) {
        int m  = f >> 5;
        int dq = (f & 31) << 2;
        *(float4*)&Qs[m * QK_STRIDE + dq] =
            *(const float4*)&g_qkv[(size_t)(qb * AT_BM + m) * QKV_OUT + h * HD + dq];
    }

    float O[32];
    #pragma unroll
    for (int u = 0; u < 32; u++) O[u] = 0.f;
    float mrow = -1e30f, lrow = 0.f;

    const int qpos = qb * AT_BM + r;
    const int ntiles = qb + 1;

    for (int kb = 0; kb < ntiles; kb++) {
        __syncthreads();
        for (int f = tid; f < AT_BN * 32; f += 256) {
            int m  = f >> 5;
            int dq = (f & 31) << 2;
            size_t gb = (size_t)(kb * AT_BN + m) * QKV_OUT + h * HD + dq;
            *(float4*)&Ks[m * QK_STRIDE + dq] = *(const float4*)&g_qkv[gb + QSIZE];
            *(float4*)&Vs[m * QK_STRIDE + dq] = *(const float4*)&g_qkv[gb + 2 * QSIZE];
        }
        __syncthreads();

        float s[16];
        #pragma unroll
        for (int jj = 0; jj < 16; jj++) s[jj] = 0.f;

        for (int d = 0; d < HD; d += 4) {
            float4 qv = *(float4*)&Qs[r * QK_STRIDE + d];
            #pragma unroll
            for (int jj = 0; jj < 16; jj++) {
                int j = c + 4 * jj;
                float4 kv = *(float4*)&Ks[j * QK_STRIDE + d];
                s[jj] += qv.x * kv.x + qv.y * kv.y + qv.z * kv.z + qv.w * kv.w;
            }
        }

        float tmax = -1e30f;
        #pragma unroll
        for (int jj = 0; jj < 16; jj++) {
            int kpos = kb * AT_BN + c + 4 * jj;
            s[jj] = (kpos <= qpos) ? s[jj] * scale : -1e30f;
            tmax = fmaxf(tmax, s[jj]);
        }
        tmax = fmaxf(tmax, __shfl_xor_sync(0xffffffffu, tmax, 1));
        tmax = fmaxf(tmax, __shfl_xor_sync(0xffffffffu, tmax, 2));

        float mnew = fmaxf(mrow, tmax);
        float psum = 0.f;
        #pragma unroll
        for (int jj = 0; jj < 16; jj++) {
            float p = __expf(s[jj] - mnew);
            Ss[r * SS_STRIDE + c + 4 * jj] = p;
            psum += p;
        }
        psum += __shfl_xor_sync(0xffffffffu, psum, 1);
        psum += __shfl_xor_sync(0xffffffffu, psum, 2);

        float alpha = __expf(mrow - mnew);
        lrow = lrow * alpha + psum;
        mrow = mnew;
        #pragma unroll
        for (int u = 0; u < 32; u++) O[u] *= alpha;

        __syncthreads();

        for (int j = 0; j < AT_BN; j++) {
            float p = Ss[r * SS_STRIDE + j];
            const float* vrow = &Vs[j * QK_STRIDE + c];
            #pragma unroll
            for (int u = 0; u < 32; u++)
                O[u] += p * vrow[4 * u];
        }
    }

    float inv = 1.0f / lrow;
    size_t ob = (size_t)qpos * QSIZE + h * HD + c;
    #pragma unroll
    for (int u = 0; u < 32; u++)
        g_attn[ob + 4 * u] = O[u] * inv;
}

// ---------------------------------------------------------------------------
extern "C" void kernel_launch(void* const* d_in, const int* in_sizes, int n_in,
                              void* d_out, int out_size)
{
    (void)in_sizes; (void)n_in; (void)out_size;
    const float* hidden    = (const float*)d_in[0];
    const int*   positions = (const int*)  d_in[1];
    const float* w_qkv     = (const float*)d_in[2];
    const float* b_qkv     = (const float*)d_in[3];
    const float* q_norm_w  = (const float*)d_in[4];
    const float* k_norm_w  = (const float*)d_in[5];
    const float* w_o       = (const float*)d_in[6];
    float*       out       = (float*)d_out;

    float *pqkv = nullptr, *pattn = nullptr;
    __nv_bfloat16 *hh, *hl, *wqh, *wql, *woh, *wol, *ath, *atl;
    cudaGetSymbolAddress((void**)&pqkv,  g_qkv);
    cudaGetSymbolAddress((void**)&pattn, g_attn);
    cudaGetSymbolAddress((void**)&hh,  g_h_hi);
    cudaGetSymbolAddress((void**)&hl,  g_h_lo);
    cudaGetSymbolAddress((void**)&wqh, g_wq_hi);
    cudaGetSymbolAddress((void**)&wql, g_wq_lo);
    cudaGetSymbolAddress((void**)&woh, g_wo_hi);
    cudaGetSymbolAddress((void**)&wol, g_wo_lo);
    cudaGetSymbolAddress((void**)&ath, g_at_hi);
    cudaGetSymbolAddress((void**)&atl, g_at_lo);

    static bool attr_set = false;
    if (!attr_set) {
        cudaFuncSetAttribute(gemm_hmma, cudaFuncAttributeMaxDynamicSharedMemorySize,
                             GEMM_SMEM);
        cudaFuncSetAttribute(attn_kernel, cudaFuncAttributeMaxDynamicSharedMemorySize,
                             (3 * AT_BM * QK_STRIDE + AT_BM * SS_STRIDE) * (int)sizeof(float));
        attr_set = true;
    }

    // 0) split inputs to bf16 hi/lo
    {
        int n4;
        n4 = (T_LEN * HIDDEN) / 4;
        split_kernel<<<(n4 + 255) / 256, 256>>>(hidden, hh, hl, n4);
        n4 = (QKV_OUT * HIDDEN) / 4;
        split_kernel<<<(n4 + 255) / 256, 256>>>(w_qkv, wqh, wql, n4);
        n4 = (HIDDEN * QSIZE) / 4;
        split_kernel<<<(n4 + 255) / 256, 256>>>(w_o, woh, wol, n4);
    }

    // 1) QKV projection + bias (HMMA bf16x3)
    {
        dim3 grid(T_LEN / 128, QKV_OUT / 256);
        gemm_hmma<<<grid, 256, GEMM_SMEM>>>(hh, hl, wqh, wql, b_qkv, pqkv, QKV_OUT);
    }

    // 2) RMSNorm + RoPE
    norm_rope_kernel<<<T_LEN, 256>>>(positions, q_norm_w, k_norm_w);

    // 3) Causal attention
    {
        const int smem_bytes = (3 * AT_BM * QK_STRIDE + AT_BM * SS_STRIDE) * sizeof(float);
        dim3 grid(T_LEN / AT_BM, NH);
        attn_kernel<<<grid, 256, smem_bytes>>>();
    }

    // 4) split attn output, then output projection (HMMA bf16x3)
    {
        int n4 = (T_LEN * QSIZE) / 4;
        split_kernel<<<(n4 + 255) / 256, 256>>>(pattn, ath, atl, n4);
        dim3 grid(T_LEN / 128, HIDDEN / 256);
        gemm_hmma<<<grid, 256, GEMM_SMEM>>>(ath, atl, woh, wol, nullptr, out, HIDDEN);
    }
}

// round 11
// speedup vs baseline: 1.8663x; 1.8663x over previous
#include <cuda_runtime.h>
#include <cuda_bf16.h>
#include <math.h>
#include <stdint.h>

#define T_LEN   2048
#define HIDDEN  4096
#define NH      32
#define HD      128
#define QSIZE   (NH*HD)          // 4096
#define QKV_OUT 12288
#define EPS     1e-5f
#define ROPE_THETA 1000000.0f

// ---------------------------------------------------------------------------
// Scratch (static device globals: allocation-free per harness rules)
// ---------------------------------------------------------------------------
__device__ float g_qkv [(size_t)T_LEN * QKV_OUT];   // QKV output, fp32
__device__ float g_attn[(size_t)T_LEN * QSIZE];     // attn output, fp32

__device__ __nv_bfloat16 g_h_hi  [(size_t)T_LEN  * HIDDEN];
__device__ __nv_bfloat16 g_h_lo  [(size_t)T_LEN  * HIDDEN];
__device__ __nv_bfloat16 g_wq_hi [(size_t)QKV_OUT * HIDDEN];
__device__ __nv_bfloat16 g_wq_lo [(size_t)QKV_OUT * HIDDEN];
__device__ __nv_bfloat16 g_wo_hi [(size_t)HIDDEN * QSIZE];
__device__ __nv_bfloat16 g_wo_lo [(size_t)HIDDEN * QSIZE];
__device__ __nv_bfloat16 g_at_hi [(size_t)T_LEN  * QSIZE];
__device__ __nv_bfloat16 g_at_lo [(size_t)T_LEN  * QSIZE];

// ---------------------------------------------------------------------------
// PTX helpers — arch-neutral (sm_80-era) only: ldmatrix, mma.sync, cp.async.
// ---------------------------------------------------------------------------
__device__ __forceinline__ uint32_t smem_u32(const void* p) {
    uint32_t a;
    asm("{ .reg .u64 t; cvta.to.shared.u64 t, %1; cvt.u32.u64 %0, t; }"
        : "=r"(a) : "l"(p));
    return a;
}

#define CP_ASYNC16(dst, src) \
    asm volatile("cp.async.cg.shared.global [%0], [%1], 16;" \
                 :: "r"(dst), "l"(src) : "memory")
#define CP_COMMIT() asm volatile("cp.async.commit_group;" ::: "memory")
template<int N>
__device__ __forceinline__ void cp_wait() {
    asm volatile("cp.async.wait_group %0;" :: "n"(N) : "memory");
}

#define LDSM_X4(R, addr) \
    asm volatile("ldmatrix.sync.aligned.m8n8.x4.shared.b16 {%0,%1,%2,%3}, [%4];" \
                 : "=r"((R)[0]), "=r"((R)[1]), "=r"((R)[2]), "=r"((R)[3]) \
                 : "r"(addr))

__device__ __forceinline__ void mma16816(float* c, const uint32_t* a,
                                         uint32_t b0, uint32_t b1) {
    asm volatile(
        "mma.sync.aligned.m16n8k16.row.col.f32.bf16.bf16.f32 "
        "{%0,%1,%2,%3}, {%4,%5,%6,%7}, {%8,%9}, {%0,%1,%2,%3};"
        : "+f"(c[0]), "+f"(c[1]), "+f"(c[2]), "+f"(c[3])
        : "r"(a[0]), "r"(a[1]), "r"(a[2]), "r"(a[3]), "r"(b0), "r"(b1));
}

// ---------------------------------------------------------------------------
// fp32 -> bf16 hi/lo split (x = hi + lo, ~16 mantissa bits total)
// ---------------------------------------------------------------------------
__global__ void split_kernel(const float* __restrict__ x,
                             __nv_bfloat16* __restrict__ hi,
                             __nv_bfloat16* __restrict__ lo, int n4)
{
    int i = blockIdx.x * blockDim.x + threadIdx.x;
    if (i >= n4) return;
    float4 v = ((const float4*)x)[i];
    __nv_bfloat16 h0 = __float2bfloat16(v.x);
    __nv_bfloat16 h1 = __float2bfloat16(v.y);
    __nv_bfloat16 h2 = __float2bfloat16(v.z);
    __nv_bfloat16 h3 = __float2bfloat16(v.w);
    __nv_bfloat16 l0 = __float2bfloat16(v.x - __bfloat162float(h0));
    __nv_bfloat16 l1 = __float2bfloat16(v.y - __bfloat162float(h1));
    __nv_bfloat16 l2 = __float2bfloat16(v.z - __bfloat162float(h2));
    __nv_bfloat16 l3 = __float2bfloat16(v.w - __bfloat162float(h3));
    __nv_bfloat162* ph = (__nv_bfloat162*)&hi[(size_t)i * 4];
    __nv_bfloat162* pl = (__nv_bfloat162*)&lo[(size_t)i * 4];
    ph[0] = __nv_bfloat162(h0, h1); ph[1] = __nv_bfloat162(h2, h3);
    pl[0] = __nv_bfloat162(l0, l1); pl[1] = __nv_bfloat162(l2, l3);
}

// ---------------------------------------------------------------------------
// HMMA bf16x3 GEMM: C[m][n] = sum_k A[m][k]*B[n][k] (+bias[n]), K = 4096.
// CTA 128x128, 8 warps (warp tile 32x64). NSTAGE=2 double buffer (81920 B)
// + __launch_bounds__(256,2) => 2 CTAs/SM (16 warps/SM): latency cover,
// which was the R5 binder (occ 12.5%, issue 23%, L1 only 26%).
// smem rows padded to 40 bf16 (80 B) -> ldmatrix conflict-free.
// ---------------------------------------------------------------------------
#define GK   4096
#define KC   32
#define KSB  80                       // bytes per smem row (40 bf16)
#define TEN  (128 * KSB)              // 10240 B per tensor tile
#define STG  (4 * TEN)                // 40960 B per stage
#define GEMM_SMEM (2 * STG)           // 81920 B

__global__ __launch_bounds__(256, 2)
void gemm_hmma(const __nv_bfloat16* __restrict__ Ah,
               const __nv_bfloat16* __restrict__ Al,
               const __nv_bfloat16* __restrict__ Bh,
               const __nv_bfloat16* __restrict__ Bl,
               const float* __restrict__ bias, float* __restrict__ C, int N)
{
    extern __shared__ char smem[];
    const uint32_t sb = smem_u32(smem);
    const int tid  = threadIdx.x;
    const int wid  = tid >> 5;
    const int lane = tid & 31;
    const int wm = (wid & 3) * 32;        // warp row offset in CTA tile
    const int wn = (wid >> 2) * 64;       // warp col offset in CTA tile
    const int bm = blockIdx.x * 128;
    const int bn = blockIdx.y * 128;

    float acc[2][8][4];
    #pragma unroll
    for (int mi = 0; mi < 2; mi++)
        #pragma unroll
        for (int ni = 0; ni < 8; ni++)
            #pragma unroll
            for (int j = 0; j < 4; j++) acc[mi][ni][j] = 0.f;

    // per-thread load coords: f in {tid, tid+256}; r=f>>2 (row), s=f&3 (16B seg)
    const int r0 = tid >> 2,         s0 = tid & 3;
    const int r1 = (tid + 256) >> 2;

    auto issue_load = [&](int c, int buf) {
        const uint32_t base = sb + (uint32_t)buf * STG;
        const int k0 = c * KC;
        {
            uint32_t doff = (uint32_t)(r0 * KSB + s0 * 16);
            size_t ga = (size_t)(bm + r0) * GK + k0 + s0 * 8;
            size_t gb = (size_t)(bn + r0) * GK + k0 + s0 * 8;
            CP_ASYNC16(base +           doff, Ah + ga);
            CP_ASYNC16(base +     TEN + doff, Al + ga);
            CP_ASYNC16(base + 2 * TEN + doff, Bh + gb);
            CP_ASYNC16(base + 3 * TEN + doff, Bl + gb);
        }
        {
            uint32_t doff = (uint32_t)(r1 * KSB + s0 * 16);
            size_t ga = (size_t)(bm + r1) * GK + k0 + s0 * 8;
            size_t gb = (size_t)(bn + r1) * GK + k0 + s0 * 8;
            CP_ASYNC16(base +           doff, Ah + ga);
            CP_ASYNC16(base +     TEN + doff, Al + ga);
            CP_ASYNC16(base + 2 * TEN + doff, Bh + gb);
            CP_ASYNC16(base + 3 * TEN + doff, Bl + gb);
        }
        CP_COMMIT();
    };

    const int NCHUNK = GK / KC;          // 128
    issue_load(0, 0);

    // ldmatrix lane addressing: row = lane&15, 16B col-group = lane>>4
    const uint32_t lrow = (uint32_t)(lane & 15) * KSB;
    const uint32_t lcol = (uint32_t)(lane >> 4) * 16;

    for (int c = 0; c < NCHUNK; c++) {
        const int buf = c & 1;
        if (c + 1 < NCHUNK) issue_load(c + 1, buf ^ 1);
        if (c + 1 < NCHUNK) cp_wait<1>(); else cp_wait<0>();
        __syncthreads();

        const uint32_t base = sb + (uint32_t)buf * STG;
        const uint32_t aA = base +           (uint32_t)wm * KSB + lrow + lcol;
        const uint32_t aB = base + 2 * TEN + (uint32_t)wn * KSB + lrow + lcol;

        #pragma unroll
        for (int ks = 0; ks < 2; ks++) {
            const uint32_t kof = ks * 32;
            uint32_t ah[2][4], al[2][4];
            #pragma unroll
            for (int mi = 0; mi < 2; mi++) {
                LDSM_X4(ah[mi], aA + mi * 16 * KSB + kof);
                LDSM_X4(al[mi], aA + TEN + mi * 16 * KSB + kof);
            }
            #pragma unroll
            for (int half = 0; half < 2; half++) {
                uint32_t bh[2][4], bl[2][4];
                #pragma unroll
                for (int p = 0; p < 2; p++) {
                    const uint32_t boff = (half * 2 + p) * 16 * KSB + kof;
                    LDSM_X4(bh[p], aB + boff);
                    LDSM_X4(bl[p], aB + TEN + boff);
                }
                // term-major: 8 distinct accumulators between same-acc reuse
                #pragma unroll
                for (int mi = 0; mi < 2; mi++)
                    #pragma unroll
                    for (int p = 0; p < 2; p++)
                        #pragma unroll
                        for (int sub = 0; sub < 2; sub++)
                            mma16816(acc[mi][half * 4 + p * 2 + sub],
                                     ah[mi], bh[p][sub], bh[p][sub + 2]);
                #pragma unroll
                for (int mi = 0; mi < 2; mi++)
                    #pragma unroll
                    for (int p = 0; p < 2; p++)
                        #pragma unroll
                        for (int sub = 0; sub < 2; sub++)
                            mma16816(acc[mi][half * 4 + p * 2 + sub],
                                     ah[mi], bl[p][sub], bl[p][sub + 2]);
                #pragma unroll
                for (int mi = 0; mi < 2; mi++)
                    #pragma unroll
                    for (int p = 0; p < 2; p++)
                        #pragma unroll
                        for (int sub = 0; sub < 2; sub++)
                            mma16816(acc[mi][half * 4 + p * 2 + sub],
                                     al[mi], bh[p][sub], bh[p][sub + 2]);
            }
        }
        __syncthreads();
    }

    // Epilogue: m16n8 acc layout: c0/c1 row=lane>>2 col=(lane&3)*2; c2/c3 row+8
    const int er = lane >> 2;
    const int ec = (lane & 3) * 2;
    #pragma unroll
    for (int mi = 0; mi < 2; mi++) {
        #pragma unroll
        for (int ni = 0; ni < 8; ni++) {
            int row = bm + wm + mi * 16 + er;
            int col = bn + wn + ni * 8 + ec;
            float b0 = bias ? bias[col] : 0.f;
            float b1 = bias ? bias[col + 1] : 0.f;
            float2 v0 = make_float2(acc[mi][ni][0] + b0, acc[mi][ni][1] + b1);
            float2 v1 = make_float2(acc[mi][ni][2] + b0, acc[mi][ni][3] + b1);
            *(float2*)&C[(size_t)row * N + col]       = v0;
            *(float2*)&C[(size_t)(row + 8) * N + col] = v1;
        }
    }
}

// ---------------------------------------------------------------------------
// Per-token RMSNorm (full 4096-dim q and k) + RoPE, in place on g_qkv.
// ---------------------------------------------------------------------------
__global__ void norm_rope_kernel(const int* __restrict__ positions,
                                 const float* __restrict__ qw,
                                 const float* __restrict__ kw)
{
    const int t   = blockIdx.x;
    const int tid = threadIdx.x;
    float* row = g_qkv + (size_t)t * QKV_OUT;

    __shared__ float red[256];
    __shared__ float s_scale_q, s_scale_k;

    float sq = 0.f, sk = 0.f;
    for (int i = tid; i < QSIZE; i += 256) {
        float x = row[i];         sq += x * x;
        float y = row[QSIZE + i]; sk += y * y;
    }

    red[tid] = sq; __syncthreads();
    for (int s = 128; s > 0; s >>= 1) {
        if (tid < s) red[tid] += red[tid + s];
        __syncthreads();
    }
    if (tid == 0) s_scale_q = rsqrtf(red[0] * (1.0f / QSIZE) + EPS);
    __syncthreads();

    red[tid] = sk; __syncthreads();
    for (int s = 128; s > 0; s >>= 1) {
        if (tid < s) red[tid] += red[tid + s];
        __syncthreads();
    }
    if (tid == 0) s_scale_k = rsqrtf(red[0] * (1.0f / QSIZE) + EPS);
    __syncthreads();

    const float scq = s_scale_q, sck = s_scale_k;
    const float pos = (float)positions[t];

    for (int idx = tid; idx < NH * 64; idx += 256) {
        int h = idx >> 6;
        int d = idx & 63;
        float inv_freq = powf(ROPE_THETA, -(float)d * (1.0f / 64.0f));
        float ang = pos * inv_freq;
        float sn, cs;
        sincosf(ang, &sn, &cs);

        int off = h * HD;
        {
            float x1 = row[off + d]      * scq * qw[off + d];
            float x2 = row[off + 64 + d] * scq * qw[off + 64 + d];
            row[off + d]      = x1 * cs - x2 * sn;
            row[off + 64 + d] = x2 * cs + x1 * sn;
        }
        {
            int offk = QSIZE + off;
            float x1 = row[offk + d]      * sck * kw[off + d];
            float x2 = row[offk + 64 + d] * sck * kw[off + 64 + d];
            row[offk + d]      = x1 * cs - x2 * sn;
            row[offk + 64 + d] = x2 * cs + x1 * sn;
        }
    }
}

// ---------------------------------------------------------------------------
// Flash-style causal attention, fp32 (known-good).
// ---------------------------------------------------------------------------
#define AT_BM 64
#define AT_BN 64
#define QK_STRIDE 132
#define SS_STRIDE 68

__global__ __launch_bounds__(256, 1)
void attn_kernel()
{
    extern __shared__ float asmem[];
    float* Qs = asmem;
    float* Ks = Qs + AT_BM * QK_STRIDE;
    float* Vs = Ks + AT_BN * QK_STRIDE;
    float* Ss = Vs + AT_BN * QK_STRIDE;

    const int qb  = blockIdx.x;
    const int h   = blockIdx.y;
    const int tid = threadIdx.x;
    const int r   = tid >> 2;
    const int c   = tid & 3;
    const float scale = 0.08838834764831845f;

    for (int f = tid; f < AT_BM * 32; f += 256) {
        int m  = f >> 5;
        int dq = (f & 31) << 2;
        *(float4*)&Qs[m * QK_STRIDE + dq] =
            *(const float4*)&g_qkv[(size_t)(qb * AT_BM + m) * QKV_OUT + h * HD + dq];
    }

    float O[32];
    #pragma unroll
    for (int u = 0; u < 32; u++) O[u] = 0.f;
    float mrow = -1e30f, lrow = 0.f;

    const int qpos = qb * AT_BM + r;
    const int ntiles = qb + 1;

    for (int kb = 0; kb < ntiles; kb++) {
        __syncthreads();
        for (int f = tid; f < AT_BN * 32; f += 256) {
            int m  = f >> 5;
            int dq = (f & 31) << 2;
            size_t gb = (size_t)(kb * AT_BN + m) * QKV_OUT + h * HD + dq;
            *(float4*)&Ks[m * QK_STRIDE + dq] = *(const float4*)&g_qkv[gb + QSIZE];
            *(float4*)&Vs[m * QK_STRIDE + dq] = *(const float4*)&g_qkv[gb + 2 * QSIZE];
        }
        __syncthreads();

        float s[16];
        #pragma unroll
        for (int jj = 0; jj < 16; jj++) s[jj] = 0.f;

        for (int d = 0; d < HD; d += 4) {
            float4 qv = *(float4*)&Qs[r * QK_STRIDE + d];
            #pragma unroll
            for (int jj = 0; jj < 16; jj++) {
                int j = c + 4 * jj;
                float4 kv = *(float4*)&Ks[j * QK_STRIDE + d];
                s[jj] += qv.x * kv.x + qv.y * kv.y + qv.z * kv.z + qv.w * kv.w;
            }
        }

        float tmax = -1e30f;
        #pragma unroll
        for (int jj = 0; jj < 16; jj++) {
            int kpos = kb * AT_BN + c + 4 * jj;
            s[jj] = (kpos <= qpos) ? s[jj] * scale : -1e30f;
            tmax = fmaxf(tmax, s[jj]);
        }
        tmax = fmaxf(tmax, __shfl_xor_sync(0xffffffffu, tmax, 1));
        tmax = fmaxf(tmax, __shfl_xor_sync(0xffffffffu, tmax, 2));

        float mnew = fmaxf(mrow, tmax);
        float psum = 0.f;
        #pragma unroll
        for (int jj = 0; jj < 16; jj++) {
            float p = __expf(s[jj] - mnew);
            Ss[r * SS_STRIDE + c + 4 * jj] = p;
            psum += p;
        }
        psum += __shfl_xor_sync(0xffffffffu, psum, 1);
        psum += __shfl_xor_sync(0xffffffffu, psum, 2);

        float alpha = __expf(mrow - mnew);
        lrow = lrow * alpha + psum;
        mrow = mnew;
        #pragma unroll
        for (int u = 0; u < 32; u++) O[u] *= alpha;

        __syncthreads();

        for (int j = 0; j < AT_BN; j++) {
            float p = Ss[r * SS_STRIDE + j];
            const float* vrow = &Vs[j * QK_STRIDE + c];
            #pragma unroll
            for (int u = 0; u < 32; u++)
                O[u] += p * vrow[4 * u];
        }
    }

    float inv = 1.0f / lrow;
    size_t ob = (size_t)qpos * QSIZE + h * HD + c;
    #pragma unroll
    for (int u = 0; u < 32; u++)
        g_attn[ob + 4 * u] = O[u] * inv;
}

// ---------------------------------------------------------------------------
extern "C" void kernel_launch(void* const* d_in, const int* in_sizes, int n_in,
                              void* d_out, int out_size)
{
    (void)in_sizes; (void)n_in; (void)out_size;
    const float* hidden    = (const float*)d_in[0];
    const int*   positions = (const int*)  d_in[1];
    const float* w_qkv     = (const float*)d_in[2];
    const float* b_qkv     = (const float*)d_in[3];
    const float* q_norm_w  = (const float*)d_in[4];
    const float* k_norm_w  = (const float*)d_in[5];
    const float* w_o       = (const float*)d_in[6];
    float*       out       = (float*)d_out;

    float *pqkv = nullptr, *pattn = nullptr;
    __nv_bfloat16 *hh, *hl, *wqh, *wql, *woh, *wol, *ath, *atl;
    cudaGetSymbolAddress((void**)&pqkv,  g_qkv);
    cudaGetSymbolAddress((void**)&pattn, g_attn);
    cudaGetSymbolAddress((void**)&hh,  g_h_hi);
    cudaGetSymbolAddress((void**)&hl,  g_h_lo);
    cudaGetSymbolAddress((void**)&wqh, g_wq_hi);
    cudaGetSymbolAddress((void**)&wql, g_wq_lo);
    cudaGetSymbolAddress((void**)&woh, g_wo_hi);
    cudaGetSymbolAddress((void**)&wol, g_wo_lo);
    cudaGetSymbolAddress((void**)&ath, g_at_hi);
    cudaGetSymbolAddress((void**)&atl, g_at_lo);

    static bool attr_set = false;
    if (!attr_set) {
        cudaFuncSetAttribute(gemm_hmma, cudaFuncAttributeMaxDynamicSharedMemorySize,
                             GEMM_SMEM);
        cudaFuncSetAttribute(attn_kernel, cudaFuncAttributeMaxDynamicSharedMemorySize,
                             (3 * AT_BM * QK_STRIDE + AT_BM * SS_STRIDE) * (int)sizeof(float));
        attr_set = true;
    }

    // 0) split inputs to bf16 hi/lo
    {
        int n4;
        n4 = (T_LEN * HIDDEN) / 4;
        split_kernel<<<(n4 + 255) / 256, 256>>>(hidden, hh, hl, n4);
        n4 = (QKV_OUT * HIDDEN) / 4;
        split_kernel<<<(n4 + 255) / 256, 256>>>(w_qkv, wqh, wql, n4);
        n4 = (HIDDEN * QSIZE) / 4;
        split_kernel<<<(n4 + 255) / 256, 256>>>(w_o, woh, wol, n4);
    }

    // 1) QKV projection + bias (HMMA bf16x3)
    {
        dim3 grid(T_LEN / 128, QKV_OUT / 128);
        gemm_hmma<<<grid, 256, GEMM_SMEM>>>(hh, hl, wqh, wql, b_qkv, pqkv, QKV_OUT);
    }

    // 2) RMSNorm + RoPE
    norm_rope_kernel<<<T_LEN, 256>>>(positions, q_norm_w, k_norm_w);

    // 3) Causal attention
    {
        const int smem_bytes = (3 * AT_BM * QK_STRIDE + AT_BM * SS_STRIDE) * sizeof(float);
        dim3 grid(T_LEN / AT_BM, NH);
        attn_kernel<<<grid, 256, smem_bytes>>>();
    }

    // 4) split attn output, then output projection (HMMA bf16x3)
    {
        int n4 = (T_LEN * QSIZE) / 4;
        split_kernel<<<(n4 + 255) / 256, 256>>>(pattn, ath, atl, n4);
        dim3 grid(T_LEN / 128, HIDDEN / 128);
        gemm_hmma<<<grid, 256, GEMM_SMEM>>>(ath, atl, woh, wol, nullptr, out, HIDDEN);
    }
}

// round 13
// speedup vs baseline: 2.1695x; 1.1625x over previous
#include <cuda_runtime.h>
#include <cuda_bf16.h>
#include <cuda_fp16.h>
#include <math.h>
#include <stdint.h>

#define T_LEN   2048
#define HIDDEN  4096
#define NH      32
#define HD      128
#define QSIZE   (NH*HD)          // 4096
#define QKV_OUT 12288
#define EPS     1e-5f
#define ROPE_THETA 1000000.0f

// ---------------------------------------------------------------------------
// Scratch (static device globals: allocation-free per harness rules)
// ---------------------------------------------------------------------------
__device__ float g_qkv [(size_t)T_LEN * QKV_OUT];   // QKV output, fp32

__device__ __nv_bfloat16 g_h_hi  [(size_t)T_LEN  * HIDDEN];
__device__ __nv_bfloat16 g_h_lo  [(size_t)T_LEN  * HIDDEN];
__device__ __nv_bfloat16 g_wq_hi [(size_t)QKV_OUT * HIDDEN];
__device__ __nv_bfloat16 g_wq_lo [(size_t)QKV_OUT * HIDDEN];
__device__ __nv_bfloat16 g_wo_hi [(size_t)HIDDEN * QSIZE];
__device__ __nv_bfloat16 g_wo_lo [(size_t)HIDDEN * QSIZE];
__device__ __nv_bfloat16 g_at_hi [(size_t)T_LEN  * QSIZE];
__device__ __nv_bfloat16 g_at_lo [(size_t)T_LEN  * QSIZE];

// head-major fp16 q/k/v for HMMA attention: [h][t][d]
__device__ __half g_qh [(size_t)NH * T_LEN * HD];
__device__ __half g_kh [(size_t)NH * T_LEN * HD];
__device__ __half g_vh [(size_t)NH * T_LEN * HD];

// ---------------------------------------------------------------------------
// PTX helpers — arch-neutral (sm_80-era) only: ldmatrix, mma.sync, cp.async.
// ---------------------------------------------------------------------------
__device__ __forceinline__ uint32_t smem_u32(const void* p) {
    uint32_t a;
    asm("{ .reg .u64 t; cvta.to.shared.u64 t, %1; cvt.u32.u64 %0, t; }"
        : "=r"(a) : "l"(p));
    return a;
}

#define CP_ASYNC16(dst, src) \
    asm volatile("cp.async.cg.shared.global [%0], [%1], 16;" \
                 :: "r"(dst), "l"(src) : "memory")
#define CP_COMMIT() asm volatile("cp.async.commit_group;" ::: "memory")
template<int N>
__device__ __forceinline__ void cp_wait() {
    asm volatile("cp.async.wait_group %0;" :: "n"(N) : "memory");
}

#define LDSM_X4(R, addr) \
    asm volatile("ldmatrix.sync.aligned.m8n8.x4.shared.b16 {%0,%1,%2,%3}, [%4];" \
                 : "=r"((R)[0]), "=r"((R)[1]), "=r"((R)[2]), "=r"((R)[3]) \
                 : "r"(addr))

#define LDSM_X4_T(R, addr) \
    asm volatile("ldmatrix.sync.aligned.m8n8.x4.trans.shared.b16 {%0,%1,%2,%3}, [%4];" \
                 : "=r"((R)[0]), "=r"((R)[1]), "=r"((R)[2]), "=r"((R)[3]) \
                 : "r"(addr))

__device__ __forceinline__ void mma16816(float* c, const uint32_t* a,
                                         uint32_t b0, uint32_t b1) {
    asm volatile(
        "mma.sync.aligned.m16n8k16.row.col.f32.bf16.bf16.f32 "
        "{%0,%1,%2,%3}, {%4,%5,%6,%7}, {%8,%9}, {%0,%1,%2,%3};"
        : "+f"(c[0]), "+f"(c[1]), "+f"(c[2]), "+f"(c[3])
        : "r"(a[0]), "r"(a[1]), "r"(a[2]), "r"(a[3]), "r"(b0), "r"(b1));
}

__device__ __forceinline__ void mma16816h(float* c, const uint32_t* a,
                                          uint32_t b0, uint32_t b1) {
    asm volatile(
        "mma.sync.aligned.m16n8k16.row.col.f32.f16.f16.f32 "
        "{%0,%1,%2,%3}, {%4,%5,%6,%7}, {%8,%9}, {%0,%1,%2,%3};"
        : "+f"(c[0]), "+f"(c[1]), "+f"(c[2]), "+f"(c[3])
        : "r"(a[0]), "r"(a[1]), "r"(a[2]), "r"(a[3]), "r"(b0), "r"(b1));
}

// ---------------------------------------------------------------------------
// fp32 -> bf16 hi/lo split (x = hi + lo, ~16 mantissa bits total)
// ---------------------------------------------------------------------------
__global__ void split_kernel(const float* __restrict__ x,
                             __nv_bfloat16* __restrict__ hi,
                             __nv_bfloat16* __restrict__ lo, int n4)
{
    int i = blockIdx.x * blockDim.x + threadIdx.x;
    if (i >= n4) return;
    float4 v = ((const float4*)x)[i];
    __nv_bfloat16 h0 = __float2bfloat16(v.x);
    __nv_bfloat16 h1 = __float2bfloat16(v.y);
    __nv_bfloat16 h2 = __float2bfloat16(v.z);
    __nv_bfloat16 h3 = __float2bfloat16(v.w);
    __nv_bfloat16 l0 = __float2bfloat16(v.x - __bfloat162float(h0));
    __nv_bfloat16 l1 = __float2bfloat16(v.y - __bfloat162float(h1));
    __nv_bfloat16 l2 = __float2bfloat16(v.z - __bfloat162float(h2));
    __nv_bfloat16 l3 = __float2bfloat16(v.w - __bfloat162float(h3));
    __nv_bfloat162* ph = (__nv_bfloat162*)&hi[(size_t)i * 4];
    __nv_bfloat162* pl = (__nv_bfloat162*)&lo[(size_t)i * 4];
    ph[0] = __nv_bfloat162(h0, h1); ph[1] = __nv_bfloat162(h2, h3);
    pl[0] = __nv_bfloat162(l0, l1); pl[1] = __nv_bfloat162(l2, l3);
}

// ---------------------------------------------------------------------------
// HMMA bf16x3 GEMM (R10/R11 winner, unchanged): CTA 128x128, 8 warps,
// NSTAGE=2, 2 CTAs/SM.
// ---------------------------------------------------------------------------
#define GK   4096
#define KC   32
#define KSB  80
#define TEN  (128 * KSB)
#define STG  (4 * TEN)
#define GEMM_SMEM (2 * STG)

__global__ __launch_bounds__(256, 2)
void gemm_hmma(const __nv_bfloat16* __restrict__ Ah,
               const __nv_bfloat16* __restrict__ Al,
               const __nv_bfloat16* __restrict__ Bh,
               const __nv_bfloat16* __restrict__ Bl,
               const float* __restrict__ bias, float* __restrict__ C, int N)
{
    extern __shared__ char smem[];
    const uint32_t sb = smem_u32(smem);
    const int tid  = threadIdx.x;
    const int wid  = tid >> 5;
    const int lane = tid & 31;
    const int wm = (wid & 3) * 32;
    const int wn = (wid >> 2) * 64;
    const int bm = blockIdx.x * 128;
    const int bn = blockIdx.y * 128;

    float acc[2][8][4];
    #pragma unroll
    for (int mi = 0; mi < 2; mi++)
        #pragma unroll
        for (int ni = 0; ni < 8; ni++)
            #pragma unroll
            for (int j = 0; j < 4; j++) acc[mi][ni][j] = 0.f;

    const int r0 = tid >> 2,         s0 = tid & 3;
    const int r1 = (tid + 256) >> 2;

    auto issue_load = [&](int c, int buf) {
        const uint32_t base = sb + (uint32_t)buf * STG;
        const int k0 = c * KC;
        {
            uint32_t doff = (uint32_t)(r0 * KSB + s0 * 16);
            size_t ga = (size_t)(bm + r0) * GK + k0 + s0 * 8;
            size_t gb = (size_t)(bn + r0) * GK + k0 + s0 * 8;
            CP_ASYNC16(base +           doff, Ah + ga);
            CP_ASYNC16(base +     TEN + doff, Al + ga);
            CP_ASYNC16(base + 2 * TEN + doff, Bh + gb);
            CP_ASYNC16(base + 3 * TEN + doff, Bl + gb);
        }
        {
            uint32_t doff = (uint32_t)(r1 * KSB + s0 * 16);
            size_t ga = (size_t)(bm + r1) * GK + k0 + s0 * 8;
            size_t gb = (size_t)(bn + r1) * GK + k0 + s0 * 8;
            CP_ASYNC16(base +           doff, Ah + ga);
            CP_ASYNC16(base +     TEN + doff, Al + ga);
            CP_ASYNC16(base + 2 * TEN + doff, Bh + gb);
            CP_ASYNC16(base + 3 * TEN + doff, Bl + gb);
        }
        CP_COMMIT();
    };

    const int NCHUNK = GK / KC;
    issue_load(0, 0);

    const uint32_t lrow = (uint32_t)(lane & 15) * KSB;
    const uint32_t lcol = (uint32_t)(lane >> 4) * 16;

    for (int c = 0; c < NCHUNK; c++) {
        const int buf = c & 1;
        if (c + 1 < NCHUNK) issue_load(c + 1, buf ^ 1);
        if (c + 1 < NCHUNK) cp_wait<1>(); else cp_wait<0>();
        __syncthreads();

        const uint32_t base = sb + (uint32_t)buf * STG;
        const uint32_t aA = base +           (uint32_t)wm * KSB + lrow + lcol;
        const uint32_t aB = base + 2 * TEN + (uint32_t)wn * KSB + lrow + lcol;

        #pragma unroll
        for (int ks = 0; ks < 2; ks++) {
            const uint32_t kof = ks * 32;
            uint32_t ah[2][4], al[2][4];
            #pragma unroll
            for (int mi = 0; mi < 2; mi++) {
                LDSM_X4(ah[mi], aA + mi * 16 * KSB + kof);
                LDSM_X4(al[mi], aA + TEN + mi * 16 * KSB + kof);
            }
            #pragma unroll
            for (int half = 0; half < 2; half++) {
                uint32_t bh[2][4], bl[2][4];
                #pragma unroll
                for (int p = 0; p < 2; p++) {
                    const uint32_t boff = (half * 2 + p) * 16 * KSB + kof;
                    LDSM_X4(bh[p], aB + boff);
                    LDSM_X4(bl[p], aB + TEN + boff);
                }
                #pragma unroll
                for (int mi = 0; mi < 2; mi++)
                    #pragma unroll
                    for (int p = 0; p < 2; p++)
                        #pragma unroll
                        for (int sub = 0; sub < 2; sub++)
                            mma16816(acc[mi][half * 4 + p * 2 + sub],
                                     ah[mi], bh[p][sub], bh[p][sub + 2]);
                #pragma unroll
                for (int mi = 0; mi < 2; mi++)
                    #pragma unroll
                    for (int p = 0; p < 2; p++)
                        #pragma unroll
                        for (int sub = 0; sub < 2; sub++)
                            mma16816(acc[mi][half * 4 + p * 2 + sub],
                                     ah[mi], bl[p][sub], bl[p][sub + 2]);
                #pragma unroll
                for (int mi = 0; mi < 2; mi++)
                    #pragma unroll
                    for (int p = 0; p < 2; p++)
                        #pragma unroll
                        for (int sub = 0; sub < 2; sub++)
                            mma16816(acc[mi][half * 4 + p * 2 + sub],
                                     al[mi], bh[p][sub], bh[p][sub + 2]);
            }
        }
        __syncthreads();
    }

    const int er = lane >> 2;
    const int ec = (lane & 3) * 2;
    #pragma unroll
    for (int mi = 0; mi < 2; mi++) {
        #pragma unroll
        for (int ni = 0; ni < 8; ni++) {
            int row = bm + wm + mi * 16 + er;
            int col = bn + wn + ni * 8 + ec;
            float b0 = bias ? bias[col] : 0.f;
            float b1 = bias ? bias[col + 1] : 0.f;
            float2 v0 = make_float2(acc[mi][ni][0] + b0, acc[mi][ni][1] + b1);
            float2 v1 = make_float2(acc[mi][ni][2] + b0, acc[mi][ni][3] + b1);
            *(float2*)&C[(size_t)row * N + col]       = v0;
            *(float2*)&C[(size_t)(row + 8) * N + col] = v1;
        }
    }
}

// ---------------------------------------------------------------------------
// Per-token RMSNorm + RoPE; emits fp16 head-major q/k/v for HMMA attention.
// ---------------------------------------------------------------------------
__global__ void norm_rope_kernel(const int* __restrict__ positions,
                                 const float* __restrict__ qw,
                                 const float* __restrict__ kw)
{
    const int t   = blockIdx.x;
    const int tid = threadIdx.x;
    const float* row = g_qkv + (size_t)t * QKV_OUT;

    __shared__ float red[256];
    __shared__ float s_scale_q, s_scale_k;

    float sq = 0.f, sk = 0.f;
    for (int i = tid; i < QSIZE; i += 256) {
        float x = row[i];         sq += x * x;
        float y = row[QSIZE + i]; sk += y * y;
    }

    red[tid] = sq; __syncthreads();
    for (int s = 128; s > 0; s >>= 1) {
        if (tid < s) red[tid] += red[tid + s];
        __syncthreads();
    }
    if (tid == 0) s_scale_q = rsqrtf(red[0] * (1.0f / QSIZE) + EPS);
    __syncthreads();

    red[tid] = sk; __syncthreads();
    for (int s = 128; s > 0; s >>= 1) {
        if (tid < s) red[tid] += red[tid + s];
        __syncthreads();
    }
    if (tid == 0) s_scale_k = rsqrtf(red[0] * (1.0f / QSIZE) + EPS);
    __syncthreads();

    const float scq = s_scale_q, sck = s_scale_k;
    const float pos = (float)positions[t];

    // v: convert to fp16 head-major
    for (int i = tid; i < QSIZE; i += 256) {
        int h = i >> 7, d = i & 127;
        g_vh[((size_t)h * T_LEN + t) * HD + d] = __float2half(row[2 * QSIZE + i]);
    }

    // q,k: norm + rope, write fp16 head-major
    for (int idx = tid; idx < NH * 64; idx += 256) {
        int h = idx >> 6;
        int d = idx & 63;
        float inv_freq = powf(ROPE_THETA, -(float)d * (1.0f / 64.0f));
        float ang = pos * inv_freq;
        float sn, cs;
        sincosf(ang, &sn, &cs);

        int off = h * HD;
        size_t hb = ((size_t)h * T_LEN + t) * HD;
        {
            float x1 = row[off + d]      * scq * qw[off + d];
            float x2 = row[off + 64 + d] * scq * qw[off + 64 + d];
            g_qh[hb + d]      = __float2half(x1 * cs - x2 * sn);
            g_qh[hb + 64 + d] = __float2half(x2 * cs + x1 * sn);
        }
        {
            int offk = QSIZE + off;
            float x1 = row[offk + d]      * sck * kw[off + d];
            float x2 = row[offk + 64 + d] * sck * kw[off + 64 + d];
            g_kh[hb + d]      = __float2half(x1 * cs - x2 * sn);
            g_kh[hb + 64 + d] = __float2half(x2 * cs + x1 * sn);
        }
    }
}

// ---------------------------------------------------------------------------
// HMMA fp16 flash attention. 128 q-rows x 64-key tiles, 8 warps (16 rows ea).
// Emits bf16 hi/lo of output directly (feeds GEMM2).
// ---------------------------------------------------------------------------
#define FA_STRIDE_B 272                      // bytes per smem row (128 h + 8 pad)
#define FA_QBYTES (128 * FA_STRIDE_B)        // 34816
#define FA_KBYTES (64 * FA_STRIDE_B)         // 17408
#define FA_SMEM   (FA_QBYTES + 4 * FA_KBYTES) // 104448

__global__ __launch_bounds__(256, 1)
void attn_hmma(const __half* __restrict__ Qg, const __half* __restrict__ Kg,
               const __half* __restrict__ Vg,
               __nv_bfloat16* __restrict__ Ohi, __nv_bfloat16* __restrict__ Olo)
{
    extern __shared__ char fsm[];
    const uint32_t sq  = smem_u32(fsm);
    const uint32_t sk0 = sq + FA_QBYTES;
    const int qb   = (int)gridDim.x - 1 - (int)blockIdx.x;  // longest-first
    const int h    = blockIdx.y;
    const int tid  = threadIdx.x;
    const int wid  = tid >> 5;
    const int lane = tid & 31;
    const int bm   = qb * 128;
    const size_t hbase = (size_t)h * T_LEN * HD;

    // Q tile: 128 rows x 256B
    {
        const __half* src = Qg + hbase + (size_t)bm * HD;
        #pragma unroll
        for (int i = 0; i < 8; i++) {
            int seg = tid + i * 256;
            int r = seg >> 4, c = seg & 15;
            CP_ASYNC16(sq + r * FA_STRIDE_B + c * 16, src + r * HD + c * 8);
        }
        CP_COMMIT();
    }

    auto load_kv = [&](int kt, int buf) {
        const uint32_t base = sk0 + (uint32_t)buf * 2 * FA_KBYTES;
        const __half* ks = Kg + hbase + (size_t)kt * 64 * HD;
        const __half* vs = Vg + hbase + (size_t)kt * 64 * HD;
        #pragma unroll
        for (int i = 0; i < 4; i++) {
            int seg = tid + i * 256;
            int r = seg >> 4, c = seg & 15;
            CP_ASYNC16(base + r * FA_STRIDE_B + c * 16, ks + r * HD + c * 8);
            CP_ASYNC16(base + FA_KBYTES + r * FA_STRIDE_B + c * 16, vs + r * HD + c * 8);
        }
        CP_COMMIT();
    };

    const int NT = 2 * qb + 2;
    load_kv(0, 0);

    float acc_o[16][4];
    #pragma unroll
    for (int i = 0; i < 16; i++)
        #pragma unroll
        for (int j = 0; j < 4; j++) acc_o[i][j] = 0.f;
    float m0 = -1e30f, m1 = -1e30f, l0 = 0.f, l1 = 0.f;
    const float scale = 0.08838834764831845f;

    const int wrow = wid * 16;
    const uint32_t qaddr = sq + (uint32_t)(wrow + (lane & 15)) * FA_STRIDE_B
                              + (uint32_t)(lane >> 4) * 16;
    const int qp0 = bm + wrow + (lane >> 2);
    const int ecl = (lane & 3) * 2;

    for (int kt = 0; kt < NT; kt++) {
        const int buf = kt & 1;
        cp_wait<0>();
        __syncthreads();
        if (kt + 1 < NT) load_kv(kt + 1, buf ^ 1);

        const uint32_t kbs = sk0 + (uint32_t)buf * 2 * FA_KBYTES;
        const uint32_t vbs = kbs + FA_KBYTES;

        // S = Q K^T  (8 n8-tiles of 64 keys)
        float s[8][4];
        #pragma unroll
        for (int j = 0; j < 8; j++)
            #pragma unroll
            for (int q = 0; q < 4; q++) s[j][q] = 0.f;

        #pragma unroll
        for (int kk = 0; kk < 8; kk++) {
            uint32_t qa[4];
            LDSM_X4(qa, qaddr + kk * 32);
            #pragma unroll
            for (int jp = 0; jp < 4; jp++) {
                uint32_t kf[4];
                LDSM_X4(kf, kbs + (uint32_t)(jp * 16 + (lane & 15)) * FA_STRIDE_B
                              + kk * 32 + (uint32_t)(lane >> 4) * 16);
                mma16816h(s[jp * 2],     qa, kf[0], kf[2]);
                mma16816h(s[jp * 2 + 1], qa, kf[1], kf[3]);
            }
        }

        // scale + causal mask + row max
        const bool domask = (kt * 64 + 63 > bm + wrow);
        const int cbase = kt * 64 + ecl;
        float t0 = -1e30f, t1 = -1e30f;
        #pragma unroll
        for (int j = 0; j < 8; j++) {
            s[j][0] *= scale; s[j][1] *= scale;
            s[j][2] *= scale; s[j][3] *= scale;
            if (domask) {
                int kp = cbase + j * 8;
                if (kp     > qp0)     s[j][0] = -1e30f;
                if (kp + 1 > qp0)     s[j][1] = -1e30f;
                if (kp     > qp0 + 8) s[j][2] = -1e30f;
                if (kp + 1 > qp0 + 8) s[j][3] = -1e30f;
            }
            t0 = fmaxf(t0, fmaxf(s[j][0], s[j][1]));
            t1 = fmaxf(t1, fmaxf(s[j][2], s[j][3]));
        }
        t0 = fmaxf(t0, __shfl_xor_sync(0xffffffffu, t0, 1));
        t0 = fmaxf(t0, __shfl_xor_sync(0xffffffffu, t0, 2));
        t1 = fmaxf(t1, __shfl_xor_sync(0xffffffffu, t1, 1));
        t1 = fmaxf(t1, __shfl_xor_sync(0xffffffffu, t1, 2));

        float mn0 = fmaxf(m0, t0), mn1 = fmaxf(m1, t1);
        float a0 = __expf(m0 - mn0), a1 = __expf(m1 - mn1);
        float ps0 = 0.f, ps1 = 0.f;
        uint32_t pf[8][2];
        #pragma unroll
        for (int j = 0; j < 8; j++) {
            float p0 = __expf(s[j][0] - mn0), p1 = __expf(s[j][1] - mn0);
            float p2 = __expf(s[j][2] - mn1), p3 = __expf(s[j][3] - mn1);
            ps0 += p0 + p1; ps1 += p2 + p3;
            __half2 h01 = __floats2half2_rn(p0, p1);
            __half2 h23 = __floats2half2_rn(p2, p3);
            pf[j][0] = *(uint32_t*)&h01;
            pf[j][1] = *(uint32_t*)&h23;
        }
        ps0 += __shfl_xor_sync(0xffffffffu, ps0, 1);
        ps0 += __shfl_xor_sync(0xffffffffu, ps0, 2);
        ps1 += __shfl_xor_sync(0xffffffffu, ps1, 1);
        ps1 += __shfl_xor_sync(0xffffffffu, ps1, 2);
        l0 = l0 * a0 + ps0; l1 = l1 * a1 + ps1;
        m0 = mn0; m1 = mn1;
        #pragma unroll
        for (int nd = 0; nd < 16; nd++) {
            acc_o[nd][0] *= a0; acc_o[nd][1] *= a0;
            acc_o[nd][2] *= a1; acc_o[nd][3] *= a1;
        }

        // O += P V   (V via ldmatrix.trans)
        #pragma unroll
        for (int j2 = 0; j2 < 4; j2++) {
            uint32_t pa[4] = { pf[2 * j2][0], pf[2 * j2][1],
                               pf[2 * j2 + 1][0], pf[2 * j2 + 1][1] };
            #pragma unroll
            for (int np = 0; np < 8; np++) {
                uint32_t vf[4];
                LDSM_X4_T(vf, vbs + (uint32_t)(j2 * 16 + (lane & 15)) * FA_STRIDE_B
                              + (uint32_t)(np * 16 + (lane >> 4) * 8) * 2);
                mma16816h(acc_o[np * 2],     pa, vf[0], vf[1]);
                mma16816h(acc_o[np * 2 + 1], pa, vf[2], vf[3]);
            }
        }
    }

    // epilogue: normalize, write bf16 hi/lo
    const float il0 = 1.0f / l0, il1 = 1.0f / l1;
    const int r0g = bm + wrow + (lane >> 2);
    const int colb = h * HD + ecl;
    #pragma unroll
    for (int nd = 0; nd < 16; nd++) {
        int col = colb + nd * 8;
        float v0 = acc_o[nd][0] * il0, v1 = acc_o[nd][1] * il0;
        float v2 = acc_o[nd][2] * il1, v3 = acc_o[nd][3] * il1;
        __nv_bfloat16 h0 = __float2bfloat16(v0), h1 = __float2bfloat16(v1);
        __nv_bfloat16 h2 = __float2bfloat16(v2), h3 = __float2bfloat16(v3);
        __nv_bfloat16 q0 = __float2bfloat16(v0 - __bfloat162float(h0));
        __nv_bfloat16 q1 = __float2bfloat16(v1 - __bfloat162float(h1));
        __nv_bfloat16 q2 = __float2bfloat16(v2 - __bfloat162float(h2));
        __nv_bfloat16 q3 = __float2bfloat16(v3 - __bfloat162float(h3));
        *(__nv_bfloat162*)&Ohi[(size_t)r0g * QSIZE + col]       = __nv_bfloat162(h0, h1);
        *(__nv_bfloat162*)&Ohi[(size_t)(r0g + 8) * QSIZE + col] = __nv_bfloat162(h2, h3);
        *(__nv_bfloat162*)&Olo[(size_t)r0g * QSIZE + col]       = __nv_bfloat162(q0, q1);
        *(__nv_bfloat162*)&Olo[(size_t)(r0g + 8) * QSIZE + col] = __nv_bfloat162(q2, q3);
    }
}

// ---------------------------------------------------------------------------
extern "C" void kernel_launch(void* const* d_in, const int* in_sizes, int n_in,
                              void* d_out, int out_size)
{
    (void)in_sizes; (void)n_in; (void)out_size;
    const float* hidden    = (const float*)d_in[0];
    const int*   positions = (const int*)  d_in[1];
    const float* w_qkv     = (const float*)d_in[2];
    const float* b_qkv     = (const float*)d_in[3];
    const float* q_norm_w  = (const float*)d_in[4];
    const float* k_norm_w  = (const float*)d_in[5];
    const float* w_o       = (const float*)d_in[6];
    float*       out       = (float*)d_out;

    float* pqkv = nullptr;
    __nv_bfloat16 *hh, *hl, *wqh, *wql, *woh, *wol, *ath, *atl;
    __half *qh, *kh, *vh;
    cudaGetSymbolAddress((void**)&pqkv, g_qkv);
    cudaGetSymbolAddress((void**)&hh,  g_h_hi);
    cudaGetSymbolAddress((void**)&hl,  g_h_lo);
    cudaGetSymbolAddress((void**)&wqh, g_wq_hi);
    cudaGetSymbolAddress((void**)&wql, g_wq_lo);
    cudaGetSymbolAddress((void**)&woh, g_wo_hi);
    cudaGetSymbolAddress((void**)&wol, g_wo_lo);
    cudaGetSymbolAddress((void**)&ath, g_at_hi);
    cudaGetSymbolAddress((void**)&atl, g_at_lo);
    cudaGetSymbolAddress((void**)&qh,  g_qh);
    cudaGetSymbolAddress((void**)&kh,  g_kh);
    cudaGetSymbolAddress((void**)&vh,  g_vh);

    static bool attr_set = false;
    if (!attr_set) {
        cudaFuncSetAttribute(gemm_hmma, cudaFuncAttributeMaxDynamicSharedMemorySize,
                             GEMM_SMEM);
        cudaFuncSetAttribute(attn_hmma, cudaFuncAttributeMaxDynamicSharedMemorySize,
                             FA_SMEM);
        attr_set = true;
    }

    // 0) split inputs to bf16 hi/lo
    {
        int n4;
        n4 = (T_LEN * HIDDEN) / 4;
        split_kernel<<<(n4 + 255) / 256, 256>>>(hidden, hh, hl, n4);
        n4 = (QKV_OUT * HIDDEN) / 4;
        split_kernel<<<(n4 + 255) / 256, 256>>>(w_qkv, wqh, wql, n4);
        n4 = (HIDDEN * QSIZE) / 4;
        split_kernel<<<(n4 + 255) / 256, 256>>>(w_o, woh, wol, n4);
    }

    // 1) QKV projection + bias (HMMA bf16x3)
    {
        dim3 grid(T_LEN / 128, QKV_OUT / 128);
        gemm_hmma<<<grid, 256, GEMM_SMEM>>>(hh, hl, wqh, wql, b_qkv, pqkv, QKV_OUT);
    }

    // 2) RMSNorm + RoPE -> fp16 head-major q/k/v
    norm_rope_kernel<<<T_LEN, 256>>>(positions, q_norm_w, k_norm_w);

    // 3) Causal attention (HMMA fp16) -> bf16 hi/lo output
    {
        dim3 grid(T_LEN / 128, NH);
        attn_hmma<<<grid, 256, FA_SMEM>>>(qh, kh, vh, ath, atl);
    }

    // 4) Output projection (HMMA bf16x3)
    {
        dim3 grid(T_LEN / 128, HIDDEN / 128);
        gemm_hmma<<<grid, 256, GEMM_SMEM>>>(ath, atl, woh, wol, nullptr, out, HIDDEN);
    }
}

// round 14
// speedup vs baseline: 4.0869x; 1.8838x over previous
#include <cuda_runtime.h>
#include <cuda_bf16.h>
#include <cuda_fp16.h>
#include <math.h>
#include <stdint.h>

#define T_LEN   2048
#define HIDDEN  4096
#define NH      32
#define HD      128
#define QSIZE   (NH*HD)          // 4096
#define QKV_OUT 12288
#define EPS     1e-5f
#define ROPE_THETA 1000000.0f

// ---------------------------------------------------------------------------
// Scratch (static device globals: allocation-free per harness rules)
// ---------------------------------------------------------------------------
__device__ float g_qkv [(size_t)T_LEN * QKV_OUT];   // QKV output, fp32

__device__ __half g_h_hi [(size_t)T_LEN  * HIDDEN];   // hidden fp16 hi
__device__ __half g_h_lo [(size_t)T_LEN  * HIDDEN];   // hidden fp16 lo
__device__ __half g_wq   [(size_t)QKV_OUT * HIDDEN];  // wqkv fp16
__device__ __half g_wo   [(size_t)HIDDEN * QSIZE];    // w_o fp16
__device__ __half g_at_hi[(size_t)T_LEN  * QSIZE];    // attn out fp16 hi
__device__ __half g_at_lo[(size_t)T_LEN  * QSIZE];    // attn out fp16 lo

// head-major fp16 q/k/v for HMMA attention: [h][t][d]
__device__ __half g_qh [(size_t)NH * T_LEN * HD];
__device__ __half g_kh [(size_t)NH * T_LEN * HD];
__device__ __half g_vh [(size_t)NH * T_LEN * HD];

// ---------------------------------------------------------------------------
// PTX helpers — arch-neutral (sm_80-era) only: ldmatrix, mma.sync, cp.async.
// ---------------------------------------------------------------------------
__device__ __forceinline__ uint32_t smem_u32(const void* p) {
    uint32_t a;
    asm("{ .reg .u64 t; cvta.to.shared.u64 t, %1; cvt.u32.u64 %0, t; }"
        : "=r"(a) : "l"(p));
    return a;
}

#define CP_ASYNC16(dst, src) \
    asm volatile("cp.async.cg.shared.global [%0], [%1], 16;" \
                 :: "r"(dst), "l"(src) : "memory")
#define CP_COMMIT() asm volatile("cp.async.commit_group;" ::: "memory")
template<int N>
__device__ __forceinline__ void cp_wait() {
    asm volatile("cp.async.wait_group %0;" :: "n"(N) : "memory");
}

#define LDSM_X4(R, addr) \
    asm volatile("ldmatrix.sync.aligned.m8n8.x4.shared.b16 {%0,%1,%2,%3}, [%4];" \
                 : "=r"((R)[0]), "=r"((R)[1]), "=r"((R)[2]), "=r"((R)[3]) \
                 : "r"(addr))

#define LDSM_X4_T(R, addr) \
    asm volatile("ldmatrix.sync.aligned.m8n8.x4.trans.shared.b16 {%0,%1,%2,%3}, [%4];" \
                 : "=r"((R)[0]), "=r"((R)[1]), "=r"((R)[2]), "=r"((R)[3]) \
                 : "r"(addr))

__device__ __forceinline__ void mma16816h(float* c, const uint32_t* a,
                                          uint32_t b0, uint32_t b1) {
    asm volatile(
        "mma.sync.aligned.m16n8k16.row.col.f32.f16.f16.f32 "
        "{%0,%1,%2,%3}, {%4,%5,%6,%7}, {%8,%9}, {%0,%1,%2,%3};"
        : "+f"(c[0]), "+f"(c[1]), "+f"(c[2]), "+f"(c[3])
        : "r"(a[0]), "r"(a[1]), "r"(a[2]), "r"(a[3]), "r"(b0), "r"(b1));
}

// ---------------------------------------------------------------------------
// fp32 -> fp16 hi/lo split (x = hi + lo, ~22 mantissa bits total)
// ---------------------------------------------------------------------------
__global__ void split16_kernel(const float* __restrict__ x,
                               __half* __restrict__ hi,
                               __half* __restrict__ lo, int n4)
{
    int i = blockIdx.x * blockDim.x + threadIdx.x;
    if (i >= n4) return;
    float4 v = ((const float4*)x)[i];
    __half h0 = __float2half(v.x), h1 = __float2half(v.y);
    __half h2 = __float2half(v.z), h3 = __float2half(v.w);
    __half l0 = __float2half(v.x - __half2float(h0));
    __half l1 = __float2half(v.y - __half2float(h1));
    __half l2 = __float2half(v.z - __half2float(h2));
    __half l3 = __float2half(v.w - __half2float(h3));
    __half2* ph = (__half2*)&hi[(size_t)i * 4];
    __half2* pl = (__half2*)&lo[(size_t)i * 4];
    ph[0] = __halves2half2(h0, h1); ph[1] = __halves2half2(h2, h3);
    pl[0] = __halves2half2(l0, l1); pl[1] = __halves2half2(l2, l3);
}

// fp32 -> fp16 plain convert (weights)
__global__ void cvt16_kernel(const float* __restrict__ x,
                             __half* __restrict__ y, int n4)
{
    int i = blockIdx.x * blockDim.x + threadIdx.x;
    if (i >= n4) return;
    float4 v = ((const float4*)x)[i];
    __half2* py = (__half2*)&y[(size_t)i * 4];
    py[0] = __halves2half2(__float2half(v.x), __float2half(v.y));
    py[1] = __halves2half2(__float2half(v.z), __float2half(v.w));
}

// ---------------------------------------------------------------------------
// HMMA fp16x2 GEMM: C[m][n] = sum_k (Ah+Al)[m][k]*B[n][k] (+bias[n]), K=4096.
// A split fp16 hi/lo (error ~2^-22), B plain fp16 (error ~2^-12).
// 2 MMA terms per tile-k (was 3 with bf16x3). CTA 128x128, 8 warps
// (warp tile 32x64), NSTAGE=2, 2 CTAs/SM (R10 skeleton).
// ---------------------------------------------------------------------------
#define GK   4096
#define KC   32
#define KSB  80                       // bytes per smem row (padded)
#define TEN  (128 * KSB)              // 10240 B per tensor tile
#define STG  (3 * TEN)                // Ah, Al, B -> 30720 B per stage
#define GEMM_SMEM (2 * STG)           // 61440 B

__global__ __launch_bounds__(256, 2)
void gemm_hmma(const __half* __restrict__ Ah,
               const __half* __restrict__ Al,
               const __half* __restrict__ B,
               const float* __restrict__ bias, float* __restrict__ C, int N)
{
    extern __shared__ char smem[];
    const uint32_t sb = smem_u32(smem);
    const int tid  = threadIdx.x;
    const int wid  = tid >> 5;
    const int lane = tid & 31;
    const int wm = (wid & 3) * 32;
    const int wn = (wid >> 2) * 64;
    const int bm = blockIdx.x * 128;
    const int bn = blockIdx.y * 128;

    float acc[2][8][4];
    #pragma unroll
    for (int mi = 0; mi < 2; mi++)
        #pragma unroll
        for (int ni = 0; ni < 8; ni++)
            #pragma unroll
            for (int j = 0; j < 4; j++) acc[mi][ni][j] = 0.f;

    // 2 threads per row, 2x16B segments each
    const int rr = tid >> 1;
    const int sbase = (tid & 1) * 2;

    auto issue_load = [&](int c, int buf) {
        const uint32_t base = sb + (uint32_t)buf * STG;
        const int k0 = c * KC;
        #pragma unroll
        for (int s = 0; s < 2; s++) {
            uint32_t doff = (uint32_t)(rr * KSB + (sbase + s) * 16);
            size_t ga = (size_t)(bm + rr) * GK + k0 + (sbase + s) * 8;
            size_t gb = (size_t)(bn + rr) * GK + k0 + (sbase + s) * 8;
            CP_ASYNC16(base +           doff, Ah + ga);
            CP_ASYNC16(base +     TEN + doff, Al + ga);
            CP_ASYNC16(base + 2 * TEN + doff, B  + gb);
        }
        CP_COMMIT();
    };

    const int NCHUNK = GK / KC;
    issue_load(0, 0);

    const uint32_t lrow = (uint32_t)(lane & 15) * KSB;
    const uint32_t lcol = (uint32_t)(lane >> 4) * 16;

    for (int c = 0; c < NCHUNK; c++) {
        const int buf = c & 1;
        if (c + 1 < NCHUNK) issue_load(c + 1, buf ^ 1);
        if (c + 1 < NCHUNK) cp_wait<1>(); else cp_wait<0>();
        __syncthreads();

        const uint32_t base = sb + (uint32_t)buf * STG;
        const uint32_t aA = base +           (uint32_t)wm * KSB + lrow + lcol;
        const uint32_t aB = base + 2 * TEN + (uint32_t)wn * KSB + lrow + lcol;

        #pragma unroll
        for (int ks = 0; ks < 2; ks++) {
            const uint32_t kof = ks * 32;
            uint32_t ah[2][4], al[2][4];
            #pragma unroll
            for (int mi = 0; mi < 2; mi++) {
                LDSM_X4(ah[mi], aA + mi * 16 * KSB + kof);
                LDSM_X4(al[mi], aA + TEN + mi * 16 * KSB + kof);
            }
            #pragma unroll
            for (int half = 0; half < 2; half++) {
                uint32_t bf[2][4];
                #pragma unroll
                for (int p = 0; p < 2; p++)
                    LDSM_X4(bf[p], aB + (half * 2 + p) * 16 * KSB + kof);
                // term 1: Ah * B   (8 distinct accumulators)
                #pragma unroll
                for (int mi = 0; mi < 2; mi++)
                    #pragma unroll
                    for (int p = 0; p < 2; p++)
                        #pragma unroll
                        for (int sub = 0; sub < 2; sub++)
                            mma16816h(acc[mi][half * 4 + p * 2 + sub],
                                      ah[mi], bf[p][sub], bf[p][sub + 2]);
                // term 2: Al * B
                #pragma unroll
                for (int mi = 0; mi < 2; mi++)
                    #pragma unroll
                    for (int p = 0; p < 2; p++)
                        #pragma unroll
                        for (int sub = 0; sub < 2; sub++)
                            mma16816h(acc[mi][half * 4 + p * 2 + sub],
                                      al[mi], bf[p][sub], bf[p][sub + 2]);
            }
        }
        __syncthreads();
    }

    const int er = lane >> 2;
    const int ec = (lane & 3) * 2;
    #pragma unroll
    for (int mi = 0; mi < 2; mi++) {
        #pragma unroll
        for (int ni = 0; ni < 8; ni++) {
            int row = bm + wm + mi * 16 + er;
            int col = bn + wn + ni * 8 + ec;
            float b0 = bias ? bias[col] : 0.f;
            float b1 = bias ? bias[col + 1] : 0.f;
            float2 v0 = make_float2(acc[mi][ni][0] + b0, acc[mi][ni][1] + b1);
            float2 v1 = make_float2(acc[mi][ni][2] + b0, acc[mi][ni][3] + b1);
            *(float2*)&C[(size_t)row * N + col]       = v0;
            *(float2*)&C[(size_t)(row + 8) * N + col] = v1;
        }
    }
}

// ---------------------------------------------------------------------------
// Per-token RMSNorm + RoPE; emits fp16 head-major q/k/v for HMMA attention.
// ---------------------------------------------------------------------------
__global__ void norm_rope_kernel(const int* __restrict__ positions,
                                 const float* __restrict__ qw,
                                 const float* __restrict__ kw)
{
    const int t   = blockIdx.x;
    const int tid = threadIdx.x;
    const float* row = g_qkv + (size_t)t * QKV_OUT;

    __shared__ float red[256];
    __shared__ float s_scale_q, s_scale_k;

    float sq = 0.f, sk = 0.f;
    for (int i = tid; i < QSIZE; i += 256) {
        float x = row[i];         sq += x * x;
        float y = row[QSIZE + i]; sk += y * y;
    }

    red[tid] = sq; __syncthreads();
    for (int s = 128; s > 0; s >>= 1) {
        if (tid < s) red[tid] += red[tid + s];
        __syncthreads();
    }
    if (tid == 0) s_scale_q = rsqrtf(red[0] * (1.0f / QSIZE) + EPS);
    __syncthreads();

    red[tid] = sk; __syncthreads();
    for (int s = 128; s > 0; s >>= 1) {
        if (tid < s) red[tid] += red[tid + s];
        __syncthreads();
    }
    if (tid == 0) s_scale_k = rsqrtf(red[0] * (1.0f / QSIZE) + EPS);
    __syncthreads();

    const float scq = s_scale_q, sck = s_scale_k;
    const float pos = (float)positions[t];

    // v: convert to fp16 head-major
    for (int i = tid; i < QSIZE; i += 256) {
        int h = i >> 7, d = i & 127;
        g_vh[((size_t)h * T_LEN + t) * HD + d] = __float2half(row[2 * QSIZE + i]);
    }

    // q,k: norm + rope, write fp16 head-major
    for (int idx = tid; idx < NH * 64; idx += 256) {
        int h = idx >> 6;
        int d = idx & 63;
        float inv_freq = powf(ROPE_THETA, -(float)d * (1.0f / 64.0f));
        float ang = pos * inv_freq;
        float sn, cs;
        sincosf(ang, &sn, &cs);

        int off = h * HD;
        size_t hb = ((size_t)h * T_LEN + t) * HD;
        {
            float x1 = row[off + d]      * scq * qw[off + d];
            float x2 = row[off + 64 + d] * scq * qw[off + 64 + d];
            g_qh[hb + d]      = __float2half(x1 * cs - x2 * sn);
            g_qh[hb + 64 + d] = __float2half(x2 * cs + x1 * sn);
        }
        {
            int offk = QSIZE + off;
            float x1 = row[offk + d]      * sck * kw[off + d];
            float x2 = row[offk + 64 + d] * sck * kw[off + 64 + d];
            g_kh[hb + d]      = __float2half(x1 * cs - x2 * sn);
            g_kh[hb + 64 + d] = __float2half(x2 * cs + x1 * sn);
        }
    }
}

// ---------------------------------------------------------------------------
// HMMA fp16 flash attention (R13 winner). 128 q-rows x 64-key tiles, 8 warps.
// Emits fp16 hi/lo of output (feeds GEMM2's split-A input).
// ---------------------------------------------------------------------------
#define FA_STRIDE_B 272                      // bytes per smem row (128 h + 8 pad)
#define FA_QBYTES (128 * FA_STRIDE_B)
#define FA_KBYTES (64 * FA_STRIDE_B)
#define FA_SMEM   (FA_QBYTES + 4 * FA_KBYTES)

__global__ __launch_bounds__(256, 1)
void attn_hmma(const __half* __restrict__ Qg, const __half* __restrict__ Kg,
               const __half* __restrict__ Vg,
               __half* __restrict__ Ohi, __half* __restrict__ Olo)
{
    extern __shared__ char fsm[];
    const uint32_t sq  = smem_u32(fsm);
    const uint32_t sk0 = sq + FA_QBYTES;
    const int qb   = (int)gridDim.x - 1 - (int)blockIdx.x;  // longest-first
    const int h    = blockIdx.y;
    const int tid  = threadIdx.x;
    const int wid  = tid >> 5;
    const int lane = tid & 31;
    const int bm   = qb * 128;
    const size_t hbase = (size_t)h * T_LEN * HD;

    // Q tile: 128 rows x 256B
    {
        const __half* src = Qg + hbase + (size_t)bm * HD;
        #pragma unroll
        for (int i = 0; i < 8; i++) {
            int seg = tid + i * 256;
            int r = seg >> 4, c = seg & 15;
            CP_ASYNC16(sq + r * FA_STRIDE_B + c * 16, src + r * HD + c * 8);
        }
        CP_COMMIT();
    }

    auto load_kv = [&](int kt, int buf) {
        const uint32_t base = sk0 + (uint32_t)buf * 2 * FA_KBYTES;
        const __half* ks = Kg + hbase + (size_t)kt * 64 * HD;
        const __half* vs = Vg + hbase + (size_t)kt * 64 * HD;
        #pragma unroll
        for (int i = 0; i < 4; i++) {
            int seg = tid + i * 256;
            int r = seg >> 4, c = seg & 15;
            CP_ASYNC16(base + r * FA_STRIDE_B + c * 16, ks + r * HD + c * 8);
            CP_ASYNC16(base + FA_KBYTES + r * FA_STRIDE_B + c * 16, vs + r * HD + c * 8);
        }
        CP_COMMIT();
    };

    const int NT = 2 * qb + 2;
    load_kv(0, 0);

    float acc_o[16][4];
    #pragma unroll
    for (int i = 0; i < 16; i++)
        #pragma unroll
        for (int j = 0; j < 4; j++) acc_o[i][j] = 0.f;
    float m0 = -1e30f, m1 = -1e30f, l0 = 0.f, l1 = 0.f;
    const float scale = 0.08838834764831845f;

    const int wrow = wid * 16;
    const uint32_t qaddr = sq + (uint32_t)(wrow + (lane & 15)) * FA_STRIDE_B
                              + (uint32_t)(lane >> 4) * 16;
    const int qp0 = bm + wrow + (lane >> 2);
    const int ecl = (lane & 3) * 2;

    for (int kt = 0; kt < NT; kt++) {
        const int buf = kt & 1;
        cp_wait<0>();
        __syncthreads();
        if (kt + 1 < NT) load_kv(kt + 1, buf ^ 1);

        const uint32_t kbs = sk0 + (uint32_t)buf * 2 * FA_KBYTES;
        const uint32_t vbs = kbs + FA_KBYTES;

        // S = Q K^T
        float s[8][4];
        #pragma unroll
        for (int j = 0; j < 8; j++)
            #pragma unroll
            for (int q = 0; q < 4; q++) s[j][q] = 0.f;

        #pragma unroll
        for (int kk = 0; kk < 8; kk++) {
            uint32_t qa[4];
            LDSM_X4(qa, qaddr + kk * 32);
            #pragma unroll
            for (int jp = 0; jp < 4; jp++) {
                uint32_t kf[4];
                LDSM_X4(kf, kbs + (uint32_t)(jp * 16 + (lane & 15)) * FA_STRIDE_B
                              + kk * 32 + (uint32_t)(lane >> 4) * 16);
                mma16816h(s[jp * 2],     qa, kf[0], kf[2]);
                mma16816h(s[jp * 2 + 1], qa, kf[1], kf[3]);
            }
        }

        // scale + causal mask + row max
        const bool domask = (kt * 64 + 63 > bm + wrow);
        const int cbase = kt * 64 + ecl;
        float t0 = -1e30f, t1 = -1e30f;
        #pragma unroll
        for (int j = 0; j < 8; j++) {
            s[j][0] *= scale; s[j][1] *= scale;
            s[j][2] *= scale; s[j][3] *= scale;
            if (domask) {
                int kp = cbase + j * 8;
                if (kp     > qp0)     s[j][0] = -1e30f;
                if (kp + 1 > qp0)     s[j][1] = -1e30f;
                if (kp     > qp0 + 8) s[j][2] = -1e30f;
                if (kp + 1 > qp0 + 8) s[j][3] = -1e30f;
            }
            t0 = fmaxf(t0, fmaxf(s[j][0], s[j][1]));
            t1 = fmaxf(t1, fmaxf(s[j][2], s[j][3]));
        }
        t0 = fmaxf(t0, __shfl_xor_sync(0xffffffffu, t0, 1));
        t0 = fmaxf(t0, __shfl_xor_sync(0xffffffffu, t0, 2));
        t1 = fmaxf(t1, __shfl_xor_sync(0xffffffffu, t1, 1));
        t1 = fmaxf(t1, __shfl_xor_sync(0xffffffffu, t1, 2));

        float mn0 = fmaxf(m0, t0), mn1 = fmaxf(m1, t1);
        float a0 = __expf(m0 - mn0), a1 = __expf(m1 - mn1);
        float ps0 = 0.f, ps1 = 0.f;
        uint32_t pf[8][2];
        #pragma unroll
        for (int j = 0; j < 8; j++) {
            float p0 = __expf(s[j][0] - mn0), p1 = __expf(s[j][1] - mn0);
            float p2 = __expf(s[j][2] - mn1), p3 = __expf(s[j][3] - mn1);
            ps0 += p0 + p1; ps1 += p2 + p3;
            __half2 h01 = __floats2half2_rn(p0, p1);
            __half2 h23 = __floats2half2_rn(p2, p3);
            pf[j][0] = *(uint32_t*)&h01;
            pf[j][1] = *(uint32_t*)&h23;
        }
        ps0 += __shfl_xor_sync(0xffffffffu, ps0, 1);
        ps0 += __shfl_xor_sync(0xffffffffu, ps0, 2);
        ps1 += __shfl_xor_sync(0xffffffffu, ps1, 1);
        ps1 += __shfl_xor_sync(0xffffffffu, ps1, 2);
        l0 = l0 * a0 + ps0; l1 = l1 * a1 + ps1;
        m0 = mn0; m1 = mn1;
        #pragma unroll
        for (int nd = 0; nd < 16; nd++) {
            acc_o[nd][0] *= a0; acc_o[nd][1] *= a0;
            acc_o[nd][2] *= a1; acc_o[nd][3] *= a1;
        }

        // O += P V
        #pragma unroll
        for (int j2 = 0; j2 < 4; j2++) {
            uint32_t pa[4] = { pf[2 * j2][0], pf[2 * j2][1],
                               pf[2 * j2 + 1][0], pf[2 * j2 + 1][1] };
            #pragma unroll
            for (int np = 0; np < 8; np++) {
                uint32_t vf[4];
                LDSM_X4_T(vf, vbs + (uint32_t)(j2 * 16 + (lane & 15)) * FA_STRIDE_B
                              + (uint32_t)(np * 16 + (lane >> 4) * 8) * 2);
                mma16816h(acc_o[np * 2],     pa, vf[0], vf[1]);
                mma16816h(acc_o[np * 2 + 1], pa, vf[2], vf[3]);
            }
        }
    }

    // epilogue: normalize, write fp16 hi/lo
    const float il0 = 1.0f / l0, il1 = 1.0f / l1;
    const int r0g = bm + wrow + (lane >> 2);
    const int colb = h * HD + ecl;
    #pragma unroll
    for (int nd = 0; nd < 16; nd++) {
        int col = colb + nd * 8;
        float v0 = acc_o[nd][0] * il0, v1 = acc_o[nd][1] * il0;
        float v2 = acc_o[nd][2] * il1, v3 = acc_o[nd][3] * il1;
        __half h0 = __float2half(v0), h1 = __float2half(v1);
        __half h2 = __float2half(v2), h3 = __float2half(v3);
        __half q0 = __float2half(v0 - __half2float(h0));
        __half q1 = __float2half(v1 - __half2float(h1));
        __half q2 = __float2half(v2 - __half2float(h2));
        __half q3 = __float2half(v3 - __half2float(h3));
        *(__half2*)&Ohi[(size_t)r0g * QSIZE + col]       = __halves2half2(h0, h1);
        *(__half2*)&Ohi[(size_t)(r0g + 8) * QSIZE + col] = __halves2half2(h2, h3);
        *(__half2*)&Olo[(size_t)r0g * QSIZE + col]       = __halves2half2(q0, q1);
        *(__half2*)&Olo[(size_t)(r0g + 8) * QSIZE + col] = __halves2half2(q2, q3);
    }
}

// ---------------------------------------------------------------------------
extern "C" void kernel_launch(void* const* d_in, const int* in_sizes, int n_in,
                              void* d_out, int out_size)
{
    (void)in_sizes; (void)n_in; (void)out_size;
    const float* hidden    = (const float*)d_in[0];
    const int*   positions = (const int*)  d_in[1];
    const float* w_qkv     = (const float*)d_in[2];
    const float* b_qkv     = (const float*)d_in[3];
    const float* q_norm_w  = (const float*)d_in[4];
    const float* k_norm_w  = (const float*)d_in[5];
    const float* w_o       = (const float*)d_in[6];
    float*       out       = (float*)d_out;

    float* pqkv = nullptr;
    __half *hh, *hl, *wq, *wo, *ath, *atl, *qh, *kh, *vh;
    cudaGetSymbolAddress((void**)&pqkv, g_qkv);
    cudaGetSymbolAddress((void**)&hh,  g_h_hi);
    cudaGetSymbolAddress((void**)&hl,  g_h_lo);
    cudaGetSymbolAddress((void**)&wq,  g_wq);
    cudaGetSymbolAddress((void**)&wo,  g_wo);
    cudaGetSymbolAddress((void**)&ath, g_at_hi);
    cudaGetSymbolAddress((void**)&atl, g_at_lo);
    cudaGetSymbolAddress((void**)&qh,  g_qh);
    cudaGetSymbolAddress((void**)&kh,  g_kh);
    cudaGetSymbolAddress((void**)&vh,  g_vh);

    static bool attr_set = false;
    if (!attr_set) {
        cudaFuncSetAttribute(gemm_hmma, cudaFuncAttributeMaxDynamicSharedMemorySize,
                             GEMM_SMEM);
        cudaFuncSetAttribute(attn_hmma, cudaFuncAttributeMaxDynamicSharedMemorySize,
                             FA_SMEM);
        attr_set = true;
    }

    // 0) prepare fp16 operands
    {
        int n4;
        n4 = (T_LEN * HIDDEN) / 4;
        split16_kernel<<<(n4 + 255) / 256, 256>>>(hidden, hh, hl, n4);
        n4 = (QKV_OUT * HIDDEN) / 4;
        cvt16_kernel<<<(n4 + 255) / 256, 256>>>(w_qkv, wq, n4);
        n4 = (HIDDEN * QSIZE) / 4;
        cvt16_kernel<<<(n4 + 255) / 256, 256>>>(w_o, wo, n4);
    }

    // 1) QKV projection + bias (HMMA fp16 2-term)
    {
        dim3 grid(T_LEN / 128, QKV_OUT / 128);
        gemm_hmma<<<grid, 256, GEMM_SMEM>>>(hh, hl, wq, b_qkv, pqkv, QKV_OUT);
    }

    // 2) RMSNorm + RoPE -> fp16 head-major q/k/v
    norm_rope_kernel<<<T_LEN, 256>>>(positions, q_norm_w, k_norm_w);

    // 3) Causal attention (HMMA fp16) -> fp16 hi/lo output
    {
        dim3 grid(T_LEN / 128, NH);
        attn_hmma<<<grid, 256, FA_SMEM>>>(qh, kh, vh, ath, atl);
    }

    // 4) Output projection (HMMA fp16 2-term)
    {
        dim3 grid(T_LEN / 128, HIDDEN / 128);
        gemm_hmma<<<grid, 256, GEMM_SMEM>>>(ath, atl, wo, nullptr, out, HIDDEN);
    }
}